// round 2
// baseline (speedup 1.0000x reference)
#include <cuda_runtime.h>
#include <math.h>

#define THREADS 256
#define NPTS 4096
#define ITER (NPTS / THREADS)   // 16
#define BATCH 2
#define INV_TAU 50.0f
#define KEXP 72.13475204444817f   // 1/(TAU*ln2), for exp(x/TAU) = exp2(x*KEXP)

#define SMEM_FLOATS (3 * NPTS + 8)
#define SMEM_BYTES (SMEM_FLOATS * sizeof(float))

// accumulators: 0 l1, 1 bce, 2 unc, 3 normal, 4 chamfer_row, 5 chamfer_col,
//               6 S-sum (EMD row), 7 T-sum (EMD col), 8 gp
__device__ float g_acc[12];
// per (batch, target point m): x = colmin*KEXP, y = coefB/Zc, z = 1 + Tc*INV_TAU
__device__ float4 g_colstats[BATCH * NPTS];

__device__ __forceinline__ float warpSum(float v) {
#pragma unroll
    for (int o = 16; o > 0; o >>= 1) v += __shfl_xor_sync(0xffffffffu, v, o);
    return v;
}
__device__ __forceinline__ float warpMin(float v) {
#pragma unroll
    for (int o = 16; o > 0; o >>= 1) v = fminf(v, __shfl_xor_sync(0xffffffffu, v, o));
    return v;
}

// Block reduction with broadcast; sh must have >= 8 floats.
__device__ __forceinline__ float blockSum(float v, float* sh) {
    __syncthreads();
    v = warpSum(v);
    int w = threadIdx.x >> 5, l = threadIdx.x & 31;
    if (l == 0) sh[w] = v;
    __syncthreads();
    if (threadIdx.x == 0) {
        float x = 0.f;
#pragma unroll
        for (int i = 0; i < THREADS / 32; i++) x += sh[i];
        sh[0] = x;
    }
    __syncthreads();
    return sh[0];
}
__device__ __forceinline__ float blockMin(float v, float* sh) {
    __syncthreads();
    v = warpMin(v);
    int w = threadIdx.x >> 5, l = threadIdx.x & 31;
    if (l == 0) sh[w] = v;
    __syncthreads();
    if (threadIdx.x == 0) {
        float x = sh[0];
#pragma unroll
        for (int i = 1; i < THREADS / 32; i++) x = fminf(x, sh[i]);
        sh[0] = x;
    }
    __syncthreads();
    return sh[0];
}

__global__ void zero_kernel() {
    if (threadIdx.x < 12) g_acc[threadIdx.x] = 0.f;
}

// ---------------- pointwise losses over B*P points ----------------
__global__ void pointwise_kernel(const float* __restrict__ sp, const float* __restrict__ st,
                                 const float* __restrict__ un, const float* __restrict__ op,
                                 const float* __restrict__ ot, const float* __restrict__ na_,
                                 const float* __restrict__ nb_, int n) {
    float s_l1 = 0.f, s_bce = 0.f, s_unc = 0.f, s_nrm = 0.f;
    for (int i = blockIdx.x * blockDim.x + threadIdx.x; i < n; i += gridDim.x * blockDim.x) {
        s_l1 += fabsf(sp[i] - st[i]);
        float p = op[i], t = ot[i];
        s_bce -= t * __logf(p) + (1.f - t) * __logf(1.f - p);
        float u = un[i];
        s_unc += u * (1.f - u);
        float ax = na_[3 * i], ay = na_[3 * i + 1], az = na_[3 * i + 2];
        float bx = nb_[3 * i], by = nb_[3 * i + 1], bz = nb_[3 * i + 2];
        float nna = sqrtf(fmaf(ax, ax, fmaf(ay, ay, az * az)));
        float nnb = sqrtf(fmaf(bx, bx, fmaf(by, by, bz * bz)));
        float cs = fmaf(ax, bx, fmaf(ay, by, az * bz)) /
                   (fmaxf(nna, 1e-8f) * fmaxf(nnb, 1e-8f));
        s_nrm += 1.f - cs;
    }
    __shared__ float sh[8];
    float v;
    v = blockSum(s_l1, sh);  if (threadIdx.x == 0) atomicAdd(&g_acc[0], v);
    v = blockSum(s_bce, sh); if (threadIdx.x == 0) atomicAdd(&g_acc[1], v);
    v = blockSum(s_unc, sh); if (threadIdx.x == 0) atomicAdd(&g_acc[2], v);
    v = blockSum(s_nrm, sh); if (threadIdx.x == 0) atomicAdd(&g_acc[3], v);
}

// -------- column stats: block = one TARGET point m; opponents = pred points --------
__global__ void colstats_kernel(const float* __restrict__ tgt, const float* __restrict__ prd) {
    int m = blockIdx.x, b = blockIdx.y;
    extern __shared__ float sm[];
    float* sx = sm;
    float* sy = sm + NPTS;
    float* sz = sm + 2 * NPTS;
    float* red = sm + 3 * NPTS;

    const float* base = prd + (size_t)b * NPTS * 3;
    // coalesced read, transposed write into x/y/z planes
    for (int j = threadIdx.x; j < 3 * NPTS; j += THREADS) {
        int pt = j / 3, c = j - 3 * pt;
        sm[c * NPTS + pt] = base[j];
    }
    const float* a = tgt + ((size_t)b * NPTS + m) * 3;
    float px = a[0], py = a[1], pz = a[2];
    __syncthreads();

    float d[ITER];
    float mn = 1e30f;
#pragma unroll
    for (int k = 0; k < ITER; k++) {
        int i = threadIdx.x + k * THREADS;
        float dx = px - sx[i], dy = py - sy[i], dz = pz - sz[i];
        float d2 = fmaxf(fmaf(dx, dx, fmaf(dy, dy, dz * dz)), 1e-12f);
        float r = rsqrtf(d2);
        d[k] = d2 * r;
        mn = fminf(mn, d[k]);
    }
    mn = blockMin(mn, red);
    float m1K = mn * KEXP;
    float Z = 0.f, Su = 0.f;
#pragma unroll
    for (int k = 0; k < ITER; k++) {
        float e = exp2f(fmaf(-d[k], KEXP, m1K));
        Z += e;
        Su = fmaf(e, d[k], Su);
    }
    Z = blockSum(Z, red);
    Su = blockSum(Su, red);
    if (threadIdx.x == 0) {
        float T = Su / Z;
        float coefB = 1.f / (float)(BATCH * NPTS);
        g_colstats[b * NPTS + m] = make_float4(m1K, coefB / Z, fmaf(T, INV_TAU, 1.f), 0.f);
        atomicAdd(&g_acc[5], mn);   // chamfer (min over n)
        atomicAdd(&g_acc[7], T);    // EMD column term
    }
}

// -------- fused row stats + gradient: block = one PRED point n --------
__global__ void rowpass_kernel(const float* __restrict__ prd, const float* __restrict__ tgt) {
    int n = blockIdx.x, b = blockIdx.y;
    extern __shared__ float sm[];
    float* sx = sm;
    float* sy = sm + NPTS;
    float* sz = sm + 2 * NPTS;
    float* red = sm + 3 * NPTS;

    const float* base = tgt + (size_t)b * NPTS * 3;
    for (int j = threadIdx.x; j < 3 * NPTS; j += THREADS) {
        int pt = j / 3, c = j - 3 * pt;
        sm[c * NPTS + pt] = base[j];
    }
    const float* a = prd + ((size_t)b * NPTS + n) * 3;
    float px = a[0], py = a[1], pz = a[2];
    __syncthreads();

    float d[ITER], id[ITER];
    float mn = 1e30f;
#pragma unroll
    for (int k = 0; k < ITER; k++) {
        int i = threadIdx.x + k * THREADS;
        float dx = px - sx[i], dy = py - sy[i], dz = pz - sz[i];
        float d2 = fmaxf(fmaf(dx, dx, fmaf(dy, dy, dz * dz)), 1e-12f);
        float r = rsqrtf(d2);
        id[k] = r;
        d[k] = d2 * r;
        mn = fminf(mn, d[k]);
    }
    mn = blockMin(mn, red);
    float m1K = mn * KEXP;
    float Z = 0.f, Su = 0.f;
#pragma unroll
    for (int k = 0; k < ITER; k++) {
        float e = exp2f(fmaf(-d[k], KEXP, m1K));
        Z += e;
        Su = fmaf(e, d[k], Su);
    }
    Z = blockSum(Z, red);
    Su = blockSum(Su, red);
    float S = Su / Z;
    float coefA = 1.f / (float)(BATCH * NPTS);
    float invZA = coefA / Z;
    float c1 = fmaf(S, INV_TAU, 1.f);   // 1 + S/tau
    if (threadIdx.x == 0) {
        atomicAdd(&g_acc[4], mn);   // chamfer (min over m)
        atomicAdd(&g_acc[6], S);    // EMD row term
    }

    const float4* __restrict__ cst = g_colstats + b * NPTS;
    float gx = 0.f, gy = 0.f, gz = 0.f;
#pragma unroll
    for (int k = 0; k < ITER; k++) {
        int i = threadIdx.x + k * THREADS;
        float4 cs = __ldg(&cst[i]);
        float dk = d[k];
        float dK = dk * KEXP;
        float er = exp2f(m1K - dK);
        float ec = exp2f(cs.x - dK);
        float dInv = dk * INV_TAU;
        float t1 = c1 - dInv;
        float t2 = cs.z - dInv;
        float G = fmaf(er * invZA, t1, ec * cs.y * t2);
        float w = G * id[k];
        float dx = px - sx[i], dy = py - sy[i], dz = pz - sz[i];
        gx = fmaf(w, dx, gx);
        gy = fmaf(w, dy, gy);
        gz = fmaf(w, dz, gz);
    }
    gx = blockSum(gx, red);
    gy = blockSum(gy, red);
    gz = blockSum(gz, red);
    if (threadIdx.x == 0) {
        float nrm = sqrtf(fmaf(gx, gx, fmaf(gy, gy, gz * gz)));
        atomicAdd(&g_acc[8], fabsf(nrm - 1.f));
    }
}

// ---------------- finalize ----------------
__global__ void final_kernel(float* __restrict__ out, int bp) {
    float invBP = 1.f / (float)bp;
    float invBN = 1.f / (float)(BATCH * NPTS);
    float l1 = g_acc[0] * invBP;
    float bce = g_acc[1] * invBP;
    float unc = g_acc[2] * invBP;
    float nrm = g_acc[3] * invBP;
    float cham = (g_acc[4] + g_acc[5]) * invBN;
    float emd = (g_acc[6] + g_acc[7]) * invBN;
    float gp = g_acc[8] * invBN;
    float pt = expf(-bce);
    float occ = 0.75f * (1.f - pt) * (1.f - pt) * bce;
    out[0] = l1 + occ + 0.1f * nrm + cham + 0.25f * emd + 0.05f * gp + 0.1f * unc;
}

extern "C" void kernel_launch(void* const* d_in, const int* in_sizes, int n_in,
                              void* d_out, int out_size) {
    const float* sdf_pred   = (const float*)d_in[0];
    const float* sdf_target = (const float*)d_in[1];
    const float* uncertainty = (const float*)d_in[2];
    const float* occ_pred   = (const float*)d_in[3];
    const float* occ_target = (const float*)d_in[4];
    const float* nrm_pred   = (const float*)d_in[5];
    const float* nrm_target = (const float*)d_in[6];
    const float* pc_pred    = (const float*)d_in[7];
    const float* pc_target  = (const float*)d_in[8];
    float* out = (float*)d_out;

    int bp = in_sizes[0];   // B * P = 200000

    // Opt in to >48KB dynamic smem (49184B needed). Non-stream API: safe under
    // graph capture, idempotent across calls.
    cudaFuncSetAttribute(colstats_kernel, cudaFuncAttributeMaxDynamicSharedMemorySize,
                         (int)SMEM_BYTES);
    cudaFuncSetAttribute(rowpass_kernel, cudaFuncAttributeMaxDynamicSharedMemorySize,
                         (int)SMEM_BYTES);

    zero_kernel<<<1, 32>>>();
    pointwise_kernel<<<448, THREADS>>>(sdf_pred, sdf_target, uncertainty,
                                       occ_pred, occ_target, nrm_pred, nrm_target, bp);
    dim3 grid(NPTS, BATCH);
    colstats_kernel<<<grid, THREADS, SMEM_BYTES>>>(pc_target, pc_pred);
    rowpass_kernel<<<grid, THREADS, SMEM_BYTES>>>(pc_pred, pc_target);
    final_kernel<<<1, 1>>>(out, bp);
}